// round 7
// baseline (speedup 1.0000x reference)
#include <cuda_runtime.h>
#include <cuda_fp16.h>
#include <mma.h>
#include <math.h>
#include <cstdint>
#include <cstdio>

using namespace nvcuda;

// Problem constants
#define DIMC   64
#define KBANK  4
#define BATCH  16
#define HIN    256
#define WIN    256
#define KSZ    5
#define HO     127
#define WO     127
#define OUT_SPATIAL (HO*WO)                       // 16129
#define OUT_OFFSET  (BATCH*DIMC*OUT_SPATIAL)      // start of w_ret in d_out

// Conv (implicit GEMM) tiling
#define BM 128          // spatial positions per block (8 oy x 16 ox)
#define BN 64           // couts per block
#define BKC 32          // cin chunk per stage
#define LDA 40          // sA leading dim (halves)  : 80 B/row
#define LDB 72          // sB leading dim (halves)  : 144 B/row
#define LDE 68          // epilogue leading dim (floats)
#define NCHUNK (KSZ*KSZ*2)   // 50
#define STAGES 4

// Scratch (static device arrays — no allocations allowed)
__device__ float  g_pooled[BATCH*DIMC];
__device__ float  g_aggb[BATCH*DIMC];
__device__ float  g_att[BATCH*KBANK];
__device__ __half g_wmat[BATCH*KSZ*KSZ*DIMC*DIMC];          // [b][s][ci][co], fp16
__device__ __half g_xh[(size_t)BATCH*HIN*WIN*DIMC];         // NHWC fp16 (128 MB)

// ---------------------------------------------------------------------------
// cp.async helpers
// ---------------------------------------------------------------------------
__device__ __forceinline__ void cp16(unsigned saddr, const void* gptr, bool pred) {
    int sz = pred ? 16 : 0;
    asm volatile("cp.async.cg.shared.global [%0], [%1], 16, %2;\n"
                 :: "r"(saddr), "l"(gptr), "r"(sz));
}
__device__ __forceinline__ void cp_commit() {
    asm volatile("cp.async.commit_group;\n");
}
template<int N> __device__ __forceinline__ void cp_wait() {
    asm volatile("cp.async.wait_group %0;\n" :: "n"(N));
}

// ---------------------------------------------------------------------------
// 0a) Zero the pooled accumulator (tiny)
// ---------------------------------------------------------------------------
__global__ void zero_pool_kernel() {
    g_pooled[threadIdx.x] = 0.f;
}

// ---------------------------------------------------------------------------
// 0b) Transpose NCHW fp32 -> NHWC fp16, fused global-avg-pool partials
// ---------------------------------------------------------------------------
__global__ __launch_bounds__(256) void transpose_kernel(const float* __restrict__ x) {
    __shared__ float s[64][65];
    const int b = blockIdx.z, h = blockIdx.y, w0 = blockIdx.x * 64;
    const int tid = threadIdx.x;
    #pragma unroll
    for (int it = 0; it < 16; it++) {
        int f = it*256 + tid;
        int c = f >> 6, wl = f & 63;
        s[c][wl] = x[(((size_t)(b*DIMC + c))*HIN + h)*WIN + w0 + wl];
    }
    __syncthreads();
    // transposed fp16 store
    #pragma unroll
    for (int it = 0; it < 8; it++) {
        int f = it*256 + tid;          // 0..2047 : (wl, c-pair)
        int wl = f >> 5, c2 = (f & 31) * 2;
        __half2 v = __floats2half2_rn(s[c2][wl], s[c2+1][wl]);
        *(__half2*)(&g_xh[(((size_t)b*HIN + h)*WIN + (w0 + wl))*DIMC + c2]) = v;
    }
    // fused pool partial: thread t -> channel c = t>>2, quarter q = t&3
    {
        int c = tid >> 2, q = tid & 3;
        float ps = 0.f;
        #pragma unroll
        for (int i = 0; i < 16; i++) ps += s[c][q*16 + i];
        ps += __shfl_xor_sync(0xffffffffu, ps, 1);
        ps += __shfl_xor_sync(0xffffffffu, ps, 2);
        if (q == 0)
            atomicAdd(&g_pooled[b*DIMC + c], ps * (1.0f / (float)(HIN*WIN)));
    }
}

// ---------------------------------------------------------------------------
// 2) Attention MLP + softmax + aggregated bias
// ---------------------------------------------------------------------------
__global__ void att_kernel(const float* __restrict__ fc1_w, const float* __restrict__ fc1_b,
                           const float* __restrict__ fc2_w, const float* __restrict__ fc2_b,
                           const float* __restrict__ bias) {
    int b = threadIdx.x;
    if (b >= BATCH) return;
    float a[KBANK];
    #pragma unroll
    for (int k = 0; k < KBANK; k++) {
        float s = fc1_b[k];
        for (int c = 0; c < DIMC; c++) s += fc1_w[k*DIMC + c] * g_pooled[b*DIMC + c];
        a[k] = fmaxf(s, 0.f);
    }
    float l[KBANK]; float mx = -1e30f;
    #pragma unroll
    for (int k = 0; k < KBANK; k++) {
        float s = fc2_b[k];
        #pragma unroll
        for (int j = 0; j < KBANK; j++) s += fc2_w[k*KBANK + j] * a[j];
        l[k] = s; mx = fmaxf(mx, s);
    }
    float den = 0.f;
    #pragma unroll
    for (int k = 0; k < KBANK; k++) { l[k] = expf(l[k] - mx); den += l[k]; }
    float inv = 1.0f / den;
    #pragma unroll
    for (int k = 0; k < KBANK; k++) { l[k] *= inv; g_att[b*KBANK + k] = l[k]; }
    for (int o = 0; o < DIMC; o++) {
        float s = 0.f;
        #pragma unroll
        for (int k = 0; k < KBANK; k++) s += l[k] * bias[k*DIMC + o];
        g_aggb[b*DIMC + o] = s;
    }
}

// ---------------------------------------------------------------------------
// 3) Mix kernel banks, coalesced. One block per (b, s) tap.
//    Phase 1 (co fastest): contiguous g_wmat stores + smem stage.
//    Phase 2 (ci fastest): contiguous w_ret stores from smem transpose.
// ---------------------------------------------------------------------------
__global__ __launch_bounds__(256) void aggw_kernel(const float* __restrict__ weight,
                                                   float* __restrict__ out) {
    __shared__ float tile[DIMC][DIMC + 1];
    const int blk = blockIdx.x;          // b*25 + s
    const int b = blk / (KSZ*KSZ);
    const int s = blk - b*(KSZ*KSZ);
    const int tid = threadIdx.x;

    float at[KBANK];
    #pragma unroll
    for (int k = 0; k < KBANK; k++) at[k] = g_att[b*KBANK + k];

    // Phase 1: t -> (ci, co), co fastest
    #pragma unroll
    for (int it = 0; it < 16; it++) {
        int t = it*256 + tid;            // 0..4095
        int ci = t >> 6, co = t & 63;
        // weight[k][co][ci][s]
        size_t base = (size_t)co*(DIMC*KSZ*KSZ) + ci*(KSZ*KSZ) + s;
        float v = 0.f;
        #pragma unroll
        for (int k = 0; k < KBANK; k++)
            v += at[k] * weight[(size_t)k*(DIMC*DIMC*KSZ*KSZ) + base];
        tile[ci][co] = v;
        g_wmat[(((size_t)b*(KSZ*KSZ) + s)*DIMC + ci)*DIMC + co] = __float2half_rn(v);
    }
    __syncthreads();
    // Phase 2: t -> (co, ci), ci fastest; w_ret[(b*64+co), s, ci]
    #pragma unroll
    for (int it = 0; it < 16; it++) {
        int t = it*256 + tid;
        int co = t >> 6, ci = t & 63;
        out[(size_t)OUT_OFFSET + ((size_t)(b*DIMC + co)*(KSZ*KSZ) + s)*DIMC + ci] =
            tile[ci][co];
    }
}

// ---------------------------------------------------------------------------
// 4) Implicit-GEMM conv, fp16 HMMA, 4-stage cp.async ring, 1 barrier/chunk.
//    Block: 128 spatial (8 oy x 16 ox) x 64 cout; K=1600 in 50 chunks of 32.
// ---------------------------------------------------------------------------
struct alignas(16) Stage { __half A[BM*LDA]; __half Bv[BKC*LDB]; };
union ConvSmem { Stage st[STAGES]; float epi[BM*LDE]; };

__global__ __launch_bounds__(256) void conv_tc_kernel(float* __restrict__ out) {
    __shared__ ConvSmem sm;

    const int b   = blockIdx.z;
    const int tx  = blockIdx.x & 7;       // ox tile (16 wide)
    const int ty  = blockIdx.x >> 3;      // oy tile (8 tall)
    const int oy0 = ty * 8;
    const int ox0 = tx * 16;

    const int tid = threadIdx.x;
    const int wid = tid >> 5;
    const int wm  = wid >> 1;             // 0..3 : spatial 32-row group
    const int wn  = wid & 1;              // 0..1 : cout 32-col group

    const __half* __restrict__ xb  = g_xh  + (size_t)b * HIN * WIN * DIMC;
    const __half* __restrict__ wbh = g_wmat + (size_t)b * (KSZ*KSZ) * DIMC * DIMC;

    wmma::fragment<wmma::accumulator, 16, 16, 16, float> acc[2][2];
    #pragma unroll
    for (int i = 0; i < 2; i++)
        #pragma unroll
        for (int j = 0; j < 2; j++) wmma::fill_fragment(acc[i][j], 0.0f);

    // Per-thread A staging geometry: 2 cp.async slots of 16B (8 halves) each.
    int aOff[2], ibY[2], ibX[2], cig8[2];
    bool vs[2];
    #pragma unroll
    for (int j = 0; j < 2; j++) {
        int f = j*256 + tid;              // 0..511  (128 pos x 4 slots)
        int pos = f >> 2, cig = f & 3;
        int py = pos >> 4, px = pos & 15;
        int oy = oy0 + py, ox = ox0 + px;
        aOff[j] = pos*LDA + cig*8;
        cig8[j] = cig*8;
        ibY[j] = oy*2 - 1; ibX[j] = ox*2 - 1;
        vs[j] = (oy < HO) && (ox < WO);
    }
    // B slot
    const int bRow = tid >> 3;
    const int bCol = (tid & 7) * 8;
    const int bOff = bRow*LDB + bCol;

    unsigned aBase[STAGES], bBase[STAGES];
    #pragma unroll
    for (int u = 0; u < STAGES; u++) {
        aBase[u] = (unsigned)__cvta_generic_to_shared(&sm.st[u].A[0]);
        bBase[u] = (unsigned)__cvta_generic_to_shared(&sm.st[u].Bv[0]);
    }

    // bias prefetch (one value per (pos-of-this-thread's epilogue column))
    // epilogue handles all couts; just cache the 64 biases via first 64 threads later.

    // issue chunk c into stage buf
    auto issue = [&](int c_, int buf_) {
        int s2 = c_ >> 1, ch = c_ & 1;
        int ky = s2 / KSZ, kx = s2 - (s2/KSZ)*KSZ;
        #pragma unroll
        for (int j = 0; j < 2; j++) {
            int iy = ibY[j] + ky, ix = ibX[j] + kx;
            bool p = vs[j] && ((unsigned)iy < HIN) && ((unsigned)ix < WIN);
            const __half* g = p ? (xb + (((size_t)iy*WIN + ix)*DIMC + ch*BKC + cig8[j])) : xb;
            cp16(aBase[buf_] + (unsigned)aOff[j]*2u, g, p);
        }
        cp16(bBase[buf_] + (unsigned)bOff*2u,
             wbh + (((size_t)s2*DIMC + ch*BKC + bRow)*DIMC + bCol), true);
        cp_commit();
    };

    issue(0, 0); issue(1, 1); issue(2, 2);

    for (int c = 0; c < NCHUNK; c++) {
        cp_wait<2>();          // group c complete (c+1, c+2 may be pending)
        __syncthreads();       // publish stage c; all warps done with stage (c-1)&3
        if (c + 3 < NCHUNK) issue(c + 3, (c + 3) & 3);
        else                cp_commit();     // keep group count uniform

        const __half* sA = sm.st[c & 3].A;
        const __half* sB = sm.st[c & 3].Bv;
        #pragma unroll
        for (int kk = 0; kk < 2; kk++) {
            wmma::fragment<wmma::matrix_a, 16, 16, 16, __half, wmma::row_major> af[2];
            wmma::fragment<wmma::matrix_b, 16, 16, 16, __half, wmma::row_major> bf[2];
            #pragma unroll
            for (int i = 0; i < 2; i++)
                wmma::load_matrix_sync(af[i], &sA[(wm*32 + i*16)*LDA + kk*16], LDA);
            #pragma unroll
            for (int j = 0; j < 2; j++)
                wmma::load_matrix_sync(bf[j], &sB[(kk*16)*LDB + wn*32 + j*16], LDB);
            #pragma unroll
            for (int i = 0; i < 2; i++)
                #pragma unroll
                for (int j = 0; j < 2; j++)
                    wmma::mma_sync(acc[i][j], af[i], bf[j], acc[i][j]);
        }
    }

    // --- epilogue: stage to smem, remap to (co, spatial), add bias ---
    __syncthreads();           // all warps done reading stages before epi overwrite
    #pragma unroll
    for (int i = 0; i < 2; i++)
        #pragma unroll
        for (int j = 0; j < 2; j++)
            wmma::store_matrix_sync(&sm.epi[(wm*32 + i*16)*LDE + wn*32 + j*16],
                                    acc[i][j], LDE, wmma::mem_row_major);
    __syncthreads();

    #pragma unroll
    for (int it = 0; it < 32; it++) {
        int idx = it*256 + tid;           // 0..8191
        int pos = idx & 127;
        int co  = idx >> 7;
        int py = pos >> 4, px = pos & 15;
        int oy = oy0 + py, ox = ox0 + px;
        if (oy < HO && ox < WO) {
            out[((size_t)(b*DIMC + co))*OUT_SPATIAL + oy*WO + ox] =
                sm.epi[pos*LDE + co] + g_aggb[b*DIMC + co];
        }
    }
}

// ---------------------------------------------------------------------------
extern "C" void kernel_launch(void* const* d_in, const int* in_sizes, int n_in,
                              void* d_out, int out_size) {
    const float* x     = (const float*)d_in[0];
    const float* fc1_w = (const float*)d_in[1];
    const float* fc1_b = (const float*)d_in[2];
    const float* fc2_w = (const float*)d_in[3];
    const float* fc2_b = (const float*)d_in[4];
    const float* weight= (const float*)d_in[5];
    const float* bias  = (const float*)d_in[6];
    float* out = (float*)d_out;

    zero_pool_kernel<<<1, BATCH*DIMC>>>();
    {
        dim3 g(WIN/64, HIN, BATCH);       // 4 x 256 x 16
        transpose_kernel<<<g, 256>>>(x);
    }
    att_kernel<<<1, 32>>>(fc1_w, fc1_b, fc2_w, fc2_b, bias);
    aggw_kernel<<<BATCH*KSZ*KSZ, 256>>>(weight, out);
    {
        dim3 grid(8 * 16, 1, BATCH);      // 128 spatial tiles x 16 samples
        conv_tc_kernel<<<grid, 256>>>(out);
    }
    (void)in_sizes; (void)n_in; (void)out_size;
}